// round 4
// baseline (speedup 1.0000x reference)
#include <cuda_runtime.h>
#include <math.h>

#define NCH   256
#define OUTSZ 7
#define GRIDY 4                  // channel splits
#define CPB   (NCH / GRIDY)      // 64 channels per block
#define NWARP 8
#define CPW   (CPB / NWARP)      // 8 channels per warp

__global__ __launch_bounds__(256, 6)
void msroi_kernel(const float* __restrict__ f0,
                  const float* __restrict__ f1,
                  const float* __restrict__ f2,
                  const float* __restrict__ f3,
                  const float* __restrict__ boxes,
                  float* __restrict__ out,
                  int nroi)
{
    const int roi = blockIdx.x;
    const int tid = threadIdx.x;

    // per-lane tap tables: 28 taps = 14 grid points x 2 bilinear taps
    __shared__ int   sxc[32];     // x column index per tap
    __shared__ float swx[32];     // x weight per tap (x 0.25 avg fold)
    __shared__ int   sry[28];     // y row offset (elements) per tap
    __shared__ float swy[28];     // y weight per tap
    __shared__ const float* sbase;
    __shared__ int sHW;

    // ---- per-ROI params (computed redundantly by all threads; cheap) ----
    const float bx1 = boxes[roi * 4 + 0];
    const float by1 = boxes[roi * 4 + 1];
    const float bx2 = boxes[roi * 4 + 2];
    const float by2 = boxes[roi * 4 + 3];

    float area = (bx2 - bx1) * (by2 - by1);
    float s    = sqrtf(fmaxf(area, 0.0f));
    float lvlf = floorf(4.0f + log2f(s / 224.0f) + 1e-6f);
    lvlf = fminf(fmaxf(lvlf, 2.0f), 5.0f);
    const int lvl = (int)lvlf - 2;                 // 0..3

    const int   Hs[4]  = {200, 100, 50, 25};
    const float scs[4] = {0.25f, 0.125f, 0.0625f, 0.03125f};
    const int   H = Hs[lvl];
    const int   W = H;
    const float scale = scs[lvl];

    if (tid < 32) {
        // ---- x tap tables (taps 28..31 zero-weight) ----
        const int g = tid;
        int   xc = 0;
        float w  = 0.0f;
        if (g < 28) {
            const int gx = g >> 1;
            const int xt = g & 1;
            const float c1 = bx1 * scale;
            const float c2 = bx2 * scale;
            const float bin = fmaxf(c2 - c1, 1.0f) / (float)OUTSZ;
            const float coord = c1 + (float)(gx >> 1) * bin
                                   + ((float)(gx & 1) + 0.5f) * bin / 2.0f;
            const bool valid = (coord >= -1.0f) && (coord <= (float)W);
            const float cc = fminf(fmaxf(coord, 0.0f), (float)(W - 1));
            const int i0 = (int)floorf(cc);
            const int i1 = min(i0 + 1, W - 1);
            const float l = cc - (float)i0;
            const float h = 1.0f - l;
            xc = xt ? i1 : i0;
            w  = valid ? (xt ? l : h) * 0.25f : 0.0f;   // fold the 1/4 bin average
        }
        sxc[g] = xc;
        swx[g] = w;
    } else if (tid < 64) {
        // ---- y tap tables ----
        const int g = tid - 32;
        if (g < 28) {
            const int gy = g >> 1;
            const int yt = g & 1;
            const float c1 = by1 * scale;
            const float c2 = by2 * scale;
            const float bin = fmaxf(c2 - c1, 1.0f) / (float)OUTSZ;
            const float coord = c1 + (float)(gy >> 1) * bin
                                   + ((float)(gy & 1) + 0.5f) * bin / 2.0f;
            const bool valid = (coord >= -1.0f) && (coord <= (float)H);
            const float cc = fminf(fmaxf(coord, 0.0f), (float)(H - 1));
            const int i0 = (int)floorf(cc);
            const int i1 = min(i0 + 1, H - 1);
            const float l = cc - (float)i0;
            const float h = 1.0f - l;
            sry[g] = (yt ? i1 : i0) * W;
            swy[g] = valid ? (yt ? l : h) : 0.0f;
        } else if (g == 28) {
            const int perB = nroi >> 1;            // B = 2
            const int b = roi / perB;
            const float* fl = (lvl == 0) ? f0 : (lvl == 1) ? f1
                            : (lvl == 2) ? f2 : f3;
            sHW = H * W;
            sbase = fl + (size_t)b * (size_t)NCH * (size_t)(H * W);
        }
    }
    __syncthreads();

    const int warp = tid >> 5;
    const int lane = tid & 31;

    const int   xc = sxc[lane];
    const float wx = swx[lane];
    const bool  act    = lane < 28;
    const bool  writer = act && ((lane & 3) == 0);

    const int HW = sHW;
    const int c0 = blockIdx.y * CPB + warp * CPW;
    const float* qbase = sbase + (size_t)c0 * HW + xc;
    float* obase = out + (size_t)roi * (NCH * OUTSZ * OUTSZ)
                       + (size_t)c0 * (OUTSZ * OUTSZ) + (lane >> 2);

    #pragma unroll 1
    for (int by = 0; by < OUTSZ; ++by) {
        // y taps for this bin-row: loaded ONCE, reused across all channels
        const int   r0 = sry[4 * by + 0];
        const int   r1 = sry[4 * by + 1];
        const int   r2 = sry[4 * by + 2];
        const int   r3 = sry[4 * by + 3];
        const float w0 = swy[4 * by + 0];
        const float w1 = swy[4 * by + 1];
        const float w2 = swy[4 * by + 2];
        const float w3 = swy[4 * by + 3];

        const float* q = qbase;
        float* o = obase + by * OUTSZ;

        #pragma unroll
        for (int i = 0; i < CPW; ++i) {
            float v0 = 0.0f, v1 = 0.0f, v2 = 0.0f, v3 = 0.0f;
            if (act) {
                v0 = __ldg(q + r0);
                v1 = __ldg(q + r1);
                v2 = __ldg(q + r2);
                v3 = __ldg(q + r3);
            }
            float a = w0 * v0;
            a = fmaf(w1, v1, a);
            a = fmaf(w2, v2, a);
            a = fmaf(w3, v3, a);
            a *= wx;

            a += __shfl_down_sync(0xffffffffu, a, 1);
            a += __shfl_down_sync(0xffffffffu, a, 2);

            if (writer) __stcs(o, a);

            q += HW;
            o += OUTSZ * OUTSZ;
        }
    }
}

extern "C" void kernel_launch(void* const* d_in, const int* in_sizes, int n_in,
                              void* d_out, int out_size)
{
    const float* f0 = (const float*)d_in[0];
    const float* f1 = (const float*)d_in[1];
    const float* f2 = (const float*)d_in[2];
    const float* f3 = (const float*)d_in[3];
    const float* bx = (const float*)d_in[4];
    float* out = (float*)d_out;

    const int nroi = in_sizes[4] / 4;              // 512
    dim3 grid(nroi, GRIDY, 1);                     // 512 x 4
    msroi_kernel<<<grid, 256>>>(f0, f1, f2, f3, bx, out, nroi);
}

// round 5
// speedup vs baseline: 1.2388x; 1.2388x over previous
#include <cuda_runtime.h>
#include <math.h>

#define NCH   256
#define OUTSZ 7
#define GRIDY 8                  // channel splits
#define CPB   (NCH / GRIDY)      // 32 channels per block
#define NWARP 8
#define CPW   (CPB / NWARP)      // 4 channels per warp

__global__ __launch_bounds__(256, 6)
void msroi_kernel(const float* __restrict__ f0,
                  const float* __restrict__ f1,
                  const float* __restrict__ f2,
                  const float* __restrict__ f3,
                  const float* __restrict__ boxes,
                  float* __restrict__ out,
                  int nroi)
{
    const int roi = blockIdx.x;
    const int tid = threadIdx.x;

    // per-lane tap tables: 28 taps = 14 grid points x 2 bilinear taps
    __shared__ __align__(16) int   sxc[32];   // x column index per tap
    __shared__ __align__(16) float swx[32];   // x weight per tap (x0.25 fold)
    __shared__ __align__(16) int   sry[28];   // y row offset (elements) per tap
    __shared__ __align__(16) float swy[28];   // y weight per tap
    __shared__ const float* sbase;
    __shared__ int sHW;

    // ---- per-ROI params (computed redundantly by all threads; cheap) ----
    const float bx1 = boxes[roi * 4 + 0];
    const float by1 = boxes[roi * 4 + 1];
    const float bx2 = boxes[roi * 4 + 2];
    const float by2 = boxes[roi * 4 + 3];

    float area = (bx2 - bx1) * (by2 - by1);
    float s    = sqrtf(fmaxf(area, 0.0f));
    float lvlf = floorf(4.0f + log2f(s / 224.0f) + 1e-6f);
    lvlf = fminf(fmaxf(lvlf, 2.0f), 5.0f);
    const int lvl = (int)lvlf - 2;                 // 0..3

    const int   Hs[4]  = {200, 100, 50, 25};
    const float scs[4] = {0.25f, 0.125f, 0.0625f, 0.03125f};
    const int   H = Hs[lvl];
    const int   W = H;
    const float scale = scs[lvl];

    if (tid < 32) {
        // ---- x tap tables (taps 28..31 zero-weight, index 0) ----
        const int g = tid;
        int   xc = 0;
        float w  = 0.0f;
        if (g < 28) {
            const int gx = g >> 1;
            const int xt = g & 1;
            const float c1 = bx1 * scale;
            const float c2 = bx2 * scale;
            const float bin = fmaxf(c2 - c1, 1.0f) / (float)OUTSZ;
            const float coord = c1 + (float)(gx >> 1) * bin
                                   + ((float)(gx & 1) + 0.5f) * bin / 2.0f;
            const bool valid = (coord >= -1.0f) && (coord <= (float)W);
            const float cc = fminf(fmaxf(coord, 0.0f), (float)(W - 1));
            const int i0 = (int)floorf(cc);
            const int i1 = min(i0 + 1, W - 1);
            const float l = cc - (float)i0;
            const float h = 1.0f - l;
            xc = xt ? i1 : i0;
            w  = valid ? (xt ? l : h) * 0.25f : 0.0f;   // fold the 1/4 bin average
        }
        sxc[g] = xc;
        swx[g] = w;
    } else if (tid < 64) {
        // ---- y tap tables ----
        const int g = tid - 32;
        if (g < 28) {
            const int gy = g >> 1;
            const int yt = g & 1;
            const float c1 = by1 * scale;
            const float c2 = by2 * scale;
            const float bin = fmaxf(c2 - c1, 1.0f) / (float)OUTSZ;
            const float coord = c1 + (float)(gy >> 1) * bin
                                   + ((float)(gy & 1) + 0.5f) * bin / 2.0f;
            const bool valid = (coord >= -1.0f) && (coord <= (float)H);
            const float cc = fminf(fmaxf(coord, 0.0f), (float)(H - 1));
            const int i0 = (int)floorf(cc);
            const int i1 = min(i0 + 1, H - 1);
            const float l = cc - (float)i0;
            const float h = 1.0f - l;
            sry[g] = (yt ? i1 : i0) * W;
            swy[g] = valid ? (yt ? l : h) : 0.0f;
        } else if (g == 28) {
            const int perB = nroi >> 1;            // B = 2
            const int b = roi / perB;
            const float* fl = (lvl == 0) ? f0 : (lvl == 1) ? f1
                            : (lvl == 2) ? f2 : f3;
            sHW = H * W;
            sbase = fl + (size_t)b * (size_t)NCH * (size_t)(H * W);
        }
    }
    __syncthreads();

    const int warp = tid >> 5;
    const int lane = tid & 31;

    const int   xc = sxc[lane];          // lanes 28..31: index 0, weight 0
    const float wx = swx[lane];
    const bool  writer = (lane < 28) && ((lane & 3) == 0);

    const int HW = sHW;
    const int c0 = blockIdx.y * CPB + warp * CPW;
    const float* q = sbase + (size_t)c0 * HW + xc;
    float* o = out + (size_t)roi * (NCH * OUTSZ * OUTSZ)
                   + (size_t)c0 * (OUTSZ * OUTSZ) + (lane >> 2);

    const int4*   sry4 = (const int4*)sry;
    const float4* swy4 = (const float4*)swy;

    #pragma unroll 1
    for (int i = 0; i < CPW; ++i) {
        #pragma unroll
        for (int by = 0; by < OUTSZ; ++by) {
            const int4   r = sry4[by];   // one LDS.128
            const float4 w = swy4[by];   // one LDS.128

            const float v0 = __ldg(q + r.x);
            const float v1 = __ldg(q + r.y);
            const float v2 = __ldg(q + r.z);
            const float v3 = __ldg(q + r.w);

            float a = w.x * v0;
            a = fmaf(w.y, v1, a);
            a = fmaf(w.z, v2, a);
            a = fmaf(w.w, v3, a);
            a *= wx;

            a += __shfl_down_sync(0xffffffffu, a, 1);
            a += __shfl_down_sync(0xffffffffu, a, 2);

            if (writer) __stcs(o + by * OUTSZ, a);
        }
        q += HW;
        o += OUTSZ * OUTSZ;
    }
}

extern "C" void kernel_launch(void* const* d_in, const int* in_sizes, int n_in,
                              void* d_out, int out_size)
{
    const float* f0 = (const float*)d_in[0];
    const float* f1 = (const float*)d_in[1];
    const float* f2 = (const float*)d_in[2];
    const float* f3 = (const float*)d_in[3];
    const float* bx = (const float*)d_in[4];
    float* out = (float*)d_out;

    const int nroi = in_sizes[4] / 4;              // 512
    dim3 grid(nroi, GRIDY, 1);                     // 512 x 8
    msroi_kernel<<<grid, 256>>>(f0, f1, f2, f3, bx, out, nroi);
}

// round 6
// speedup vs baseline: 1.3820x; 1.1156x over previous
#include <cuda_runtime.h>
#include <math.h>

#define NCH   256
#define OUTSZ 7
#define GRIDY 8                  // channel splits
#define CPB   (NCH / GRIDY)      // 32 channels per block
#define NWARP 8
#define CPW   (CPB / NWARP)      // 4 channels per warp

__global__ __launch_bounds__(256, 6)
void msroi_kernel(const float* __restrict__ f0,
                  const float* __restrict__ f1,
                  const float* __restrict__ f2,
                  const float* __restrict__ f3,
                  const float* __restrict__ boxes,
                  float* __restrict__ out,
                  int nroi)
{
    const int roi = blockIdx.x;
    const int tid = threadIdx.x;

    // per-lane tap tables: 28 taps = 14 grid points x 2 bilinear taps
    __shared__ __align__(16) int   sxc[32];   // x column index per tap
    __shared__ __align__(16) float swx[32];   // x weight per tap (x0.25 fold)
    __shared__ __align__(16) int   sry[28];   // y row offset (elements) per tap
    __shared__ __align__(16) float swy[28];   // y weight per tap
    __shared__ const float* sbase;
    __shared__ int sHW;

    // ---- per-ROI params (computed redundantly by all threads; cheap) ----
    const float bx1 = boxes[roi * 4 + 0];
    const float by1 = boxes[roi * 4 + 1];
    const float bx2 = boxes[roi * 4 + 2];
    const float by2 = boxes[roi * 4 + 3];

    float area = (bx2 - bx1) * (by2 - by1);
    float s    = sqrtf(fmaxf(area, 0.0f));
    float lvlf = floorf(4.0f + log2f(s / 224.0f) + 1e-6f);
    lvlf = fminf(fmaxf(lvlf, 2.0f), 5.0f);
    const int lvl = (int)lvlf - 2;                 // 0..3

    const int   Hs[4]  = {200, 100, 50, 25};
    const float scs[4] = {0.25f, 0.125f, 0.0625f, 0.03125f};
    const int   H = Hs[lvl];
    const int   W = H;
    const float scale = scs[lvl];

    if (tid < 32) {
        // ---- x tap tables (taps 28..31 zero-weight, index 0) ----
        const int g = tid;
        int   xc = 0;
        float w  = 0.0f;
        if (g < 28) {
            const int gx = g >> 1;
            const int xt = g & 1;
            const float c1 = bx1 * scale;
            const float c2 = bx2 * scale;
            const float bin = fmaxf(c2 - c1, 1.0f) / (float)OUTSZ;
            const float coord = c1 + (float)(gx >> 1) * bin
                                   + ((float)(gx & 1) + 0.5f) * bin / 2.0f;
            const bool valid = (coord >= -1.0f) && (coord <= (float)W);
            const float cc = fminf(fmaxf(coord, 0.0f), (float)(W - 1));
            const int i0 = (int)floorf(cc);
            const int i1 = min(i0 + 1, W - 1);
            const float l = cc - (float)i0;
            const float h = 1.0f - l;
            xc = xt ? i1 : i0;
            w  = valid ? (xt ? l : h) * 0.25f : 0.0f;   // fold the 1/4 bin average
        }
        sxc[g] = xc;
        swx[g] = w;
    } else if (tid < 64) {
        // ---- y tap tables ----
        const int g = tid - 32;
        if (g < 28) {
            const int gy = g >> 1;
            const int yt = g & 1;
            const float c1 = by1 * scale;
            const float c2 = by2 * scale;
            const float bin = fmaxf(c2 - c1, 1.0f) / (float)OUTSZ;
            const float coord = c1 + (float)(gy >> 1) * bin
                                   + ((float)(gy & 1) + 0.5f) * bin / 2.0f;
            const bool valid = (coord >= -1.0f) && (coord <= (float)H);
            const float cc = fminf(fmaxf(coord, 0.0f), (float)(H - 1));
            const int i0 = (int)floorf(cc);
            const int i1 = min(i0 + 1, H - 1);
            const float l = cc - (float)i0;
            const float h = 1.0f - l;
            sry[g] = (yt ? i1 : i0) * W;
            swy[g] = valid ? (yt ? l : h) : 0.0f;
        } else if (g == 28) {
            const int perB = nroi >> 1;            // B = 2
            const int b = roi / perB;
            const float* fl = (lvl == 0) ? f0 : (lvl == 1) ? f1
                            : (lvl == 2) ? f2 : f3;
            sHW = H * W;
            sbase = fl + (size_t)b * (size_t)NCH * (size_t)(H * W);
        }
    }
    __syncthreads();

    const int warp = tid >> 5;
    const int lane = tid & 31;

    const int   xc = sxc[lane];
    const float wx = swx[lane];
    const bool  act    = lane < 28;     // lanes 28..31 fully predicated off
    const bool  writer = act && ((lane & 3) == 0);

    const int HW = sHW;
    const int c0 = blockIdx.y * CPB + warp * CPW;
    const float* q = sbase + (size_t)c0 * HW + xc;
    float* o = out + (size_t)roi * (NCH * OUTSZ * OUTSZ)
                   + (size_t)c0 * (OUTSZ * OUTSZ) + (lane >> 2);

    const int4*   sry4 = (const int4*)sry;
    const float4* swy4 = (const float4*)swy;

    #pragma unroll 1
    for (int i = 0; i < CPW; ++i) {
        #pragma unroll
        for (int by = 0; by < OUTSZ; ++by) {
            const int4   r = sry4[by];   // one LDS.128
            const float4 w = swy4[by];   // one LDS.128

            float a = 0.0f;
            if (act) {
                const float v0 = __ldg(q + r.x);
                const float v1 = __ldg(q + r.y);
                const float v2 = __ldg(q + r.z);
                const float v3 = __ldg(q + r.w);
                a = w.x * v0;
                a = fmaf(w.y, v1, a);
                a = fmaf(w.z, v2, a);
                a = fmaf(w.w, v3, a);
                a *= wx;
            }

            a += __shfl_down_sync(0xffffffffu, a, 1);
            a += __shfl_down_sync(0xffffffffu, a, 2);

            if (writer) __stcs(o + by * OUTSZ, a);
        }
        q += HW;
        o += OUTSZ * OUTSZ;
    }
}

extern "C" void kernel_launch(void* const* d_in, const int* in_sizes, int n_in,
                              void* d_out, int out_size)
{
    const float* f0 = (const float*)d_in[0];
    const float* f1 = (const float*)d_in[1];
    const float* f2 = (const float*)d_in[2];
    const float* f3 = (const float*)d_in[3];
    const float* bx = (const float*)d_in[4];
    float* out = (float*)d_out;

    const int nroi = in_sizes[4] / 4;              // 512
    dim3 grid(nroi, GRIDY, 1);                     // 512 x 8
    msroi_kernel<<<grid, 256>>>(f0, f1, f2, f3, bx, out, nroi);
}